// round 16
// baseline (speedup 1.0000x reference)
#include <cuda_runtime.h>

// CANN recurrent net — single persistent kernel, tree-barrier grid sync.
//   step t: y = J @ s_{t-1};  U = y/recSum_{t-1} + Iext;  s_t = (0.2 U)^2
//   outputs: U_14 (1680), recSum_14 (1), r_14 = s_14/recSum_14 (1680)
//
// 148 CTAs x 384 thr (1 CTA/SM), 1 warp = 1 row, J register-resident for the
// WHOLE run. Grid barrier redesigned around the measured LTS atomic law
// (same-address atomics serialize ~27cyc): arrivals spread over 8 cell
// counters on distinct 128B lines (<=19 serialized each), cell-last arrives
// on a root (8 atomics), root-last releases a single flag; one thread per CTA
// spins on the flag (others parked at bar.sync). All counters/flags are
// monotonic; the replay id is the settled g_flag[ITERS] of the previous
// replay (graph replays are stream-serialized) -> zero entry atomics.

#define Nn     1680
#define NBLK   148
#define TPB    384          // 12 warps
#define ITERS  14
#define KC     0.005f

__device__ float    g_s[2][Nn];               // s vectors, parity-buffered
__device__ unsigned g_cell[ITERS + 1][8 * 32]; // 8 cells/step, 128B apart
__device__ unsigned g_root[ITERS + 1];        // per-step root counters
__device__ unsigned g_flag[ITERS + 1];        // per-step completion flags

__device__ __forceinline__ float4 ldcg4(const float4* p) {
    float4 v;
    asm volatile("ld.global.cg.v4.f32 {%0,%1,%2,%3}, [%4];"
                 : "=f"(v.x), "=f"(v.y), "=f"(v.z), "=f"(v.w) : "l"(p));
    return v;
}
__device__ __forceinline__ void stcg(float* p, float v) {
    asm volatile("st.global.cg.f32 [%0], %1;" :: "l"(p), "f"(v) : "memory");
}
__device__ __forceinline__ unsigned ldcg32(const unsigned* p) {
    unsigned v;
    asm volatile("ld.global.cg.u32 %0, [%1];" : "=r"(v) : "l"(p));
    return v;
}
__device__ __forceinline__ unsigned atom_add_release(unsigned* p, unsigned v) {
    unsigned old;
    asm volatile("atom.release.gpu.global.add.u32 %0, [%1], %2;"
                 : "=r"(old) : "l"(p), "r"(v) : "memory");
    return old;
}
__device__ __forceinline__ unsigned ld_acquire(const unsigned* p) {
    unsigned v;
    asm volatile("ld.acquire.gpu.global.u32 %0, [%1];" : "=r"(v) : "l"(p) : "memory");
    return v;
}
__device__ __forceinline__ void st_release(unsigned* p, unsigned v) {
    asm volatile("st.release.gpu.global.u32 [%0], %1;" :: "l"(p), "r"(v) : "memory");
}

__global__ void __launch_bounds__(TPB, 1)
cann_kernel(const float* __restrict__ net_in,
            const float* __restrict__ J,
            float* __restrict__ out)
{
    __shared__ __align__(16) float s_sm[Nn];
    __shared__ float s_part[12];

    const int tid  = threadIdx.x;
    const int lane = tid & 31;
    const int wid  = tid >> 5;
    const int bid  = blockIdx.x;
    const int row  = wid * NBLK + bid;          // 12*148 = 1776 >= 1680
    const bool active = (row < Nn);

    // Replay id: settled final flag of the previous replay (stream-serialized).
    // Every CTA reads it before any barrier of this replay can complete.
    const unsigned run = ldcg32(&g_flag[ITERS]);
    const unsigned tag = run + 1u;

    // ---- J row -> registers once for the whole run (1680 = 13*128 + 16) ----
    float4 Jr[13];
    float jtail = 0.f, iext = 0.f;
    if (active) {
        iext = __ldg(&net_in[row]);
        const float* Jrow = J + (size_t)row * Nn;
        const float4* Jp = reinterpret_cast<const float4*>(Jrow);
        #pragma unroll
        for (int j = 0; j < 13; ++j) Jr[j] = __ldg(&Jp[j * 32 + lane]);
        if (lane < 16) jtail = __ldg(&Jrow[1664 + lane]);
    }

    // ---- stage s_0 = r0 ----
    {
        const float4* r4 = reinterpret_cast<const float4*>(net_in + Nn);
        #pragma unroll
        for (int k = 0; k < 2; ++k) {
            int i = tid + k * TPB;
            if (i < Nn / 4) reinterpret_cast<float4*>(s_sm)[i] = __ldg(&r4[i]);
        }
    }
    __syncthreads();

    const int cell       = bid & 7;               // cells 0-3: 19 CTAs, 4-7: 18
    const unsigned csize = (cell < 4) ? 19u : 18u;

    for (int t = 1; t <= ITERS; ++t) {
        // ---- matvec (register J row x smem s_{t-1}) with fused recSum ----
        if (active) {
            const float4* s4 = reinterpret_cast<const float4*>(s_sm);
            float a0 = 0.f, a1 = 0.f, rs = 0.f;
            #pragma unroll
            for (int j = 0; j < 13; ++j) {
                float4 b = s4[j * 32 + lane];
                rs += (b.x + b.y) + (b.z + b.w);
                if (j & 1) {
                    a1 = fmaf(Jr[j].x, b.x, a1); a1 = fmaf(Jr[j].y, b.y, a1);
                    a1 = fmaf(Jr[j].z, b.z, a1); a1 = fmaf(Jr[j].w, b.w, a1);
                } else {
                    a0 = fmaf(Jr[j].x, b.x, a0); a0 = fmaf(Jr[j].y, b.y, a0);
                    a0 = fmaf(Jr[j].z, b.z, a0); a0 = fmaf(Jr[j].w, b.w, a0);
                }
            }
            if (lane < 16) {
                float bt = s_sm[1664 + lane];
                rs += bt;
                a1 = fmaf(jtail, bt, a1);
            }
            float acc = a0 + a1;
            #pragma unroll
            for (int o = 16; o; o >>= 1) {
                acc += __shfl_xor_sync(0xffffffffu, acc, o);
                rs  += __shfl_xor_sync(0xffffffffu, rs,  o);
            }
            if (lane == 0) {
                const float invDen = (t == 1) ? 1.0f : 1.0f / (KC * rs);
                float U  = fmaf(acc, invDen, iext);
                float u2 = 0.2f * U;
                float sv = u2 * u2;
                stcg(&g_s[t & 1][row], sv);
                if (t == ITERS) out[row] = U;        // U_14
            }
        }

        // ---- tree barrier: cell atomic -> root atomic -> flag; 1-thread spin
        __syncthreads();   // all 12 rows of this CTA published
        if (tid == 0) {
            unsigned old = atom_add_release(&g_cell[t][cell * 32], 1u);
            if (old == run * csize + (csize - 1u)) {
                unsigned ro = atom_add_release(&g_root[t], 1u);
                if (ro == run * 8u + 7u) st_release(&g_flag[t], tag);
            }
            while ((int)(ld_acquire(&g_flag[t]) - tag) < 0) { /* spin */ }
        }
        __syncthreads();   // 11 warps were parked here, zero issue pressure

        // ---- stage s_t for the next iteration ----
        if (t < ITERS) {
            const float4* sp = reinterpret_cast<const float4*>(g_s[t & 1]);
            #pragma unroll
            for (int k = 0; k < 2; ++k) {
                int i = tid + k * TPB;
                if (i < Nn / 4) reinterpret_cast<float4*>(s_sm)[i] = ldcg4(&sp[i]);
            }
            __syncthreads();
        }
    }

    // ---- epilogue (CTA 0 only): recSum_14, r_14 ----
    if (bid == 0) {
        const float4* sp = reinterpret_cast<const float4*>(g_s[ITERS & 1]);
        float4 a = ldcg4(&sp[tid]);                   // tid < 384 < 420
        float4 b = make_float4(0.f, 0.f, 0.f, 0.f);
        const bool has2 = (tid + TPB) < Nn / 4;       // tid < 36
        if (has2) b = ldcg4(&sp[tid + TPB]);
        float v = ((a.x + a.y) + (a.z + a.w)) + ((b.x + b.y) + (b.z + b.w));
        #pragma unroll
        for (int o = 16; o; o >>= 1) v += __shfl_xor_sync(0xffffffffu, v, o);
        if (lane == 0) s_part[wid] = v;
        __syncthreads();
        float rsum = 0.f;
        #pragma unroll
        for (int w = 0; w < 12; ++w) rsum += s_part[w];
        const float recS = KC * rsum;

        if (tid == 0) out[Nn] = recS;                 // recSum_14
        float* r14 = out + Nn + 1;                    // r_14
        r14[4 * tid + 0] = a.x / recS;
        r14[4 * tid + 1] = a.y / recS;
        r14[4 * tid + 2] = a.z / recS;
        r14[4 * tid + 3] = a.w / recS;
        if (has2) {
            r14[4 * (tid + TPB) + 0] = b.x / recS;
            r14[4 * (tid + TPB) + 1] = b.y / recS;
            r14[4 * (tid + TPB) + 2] = b.z / recS;
            r14[4 * (tid + TPB) + 3] = b.w / recS;
        }
    }
}

extern "C" void kernel_launch(void* const* d_in, const int* in_sizes, int n_in,
                              void* d_out, int out_size)
{
    const float* a = (const float*)d_in[0];
    const float* b = (const float*)d_in[1];
    const float* net_in = a;
    const float* J      = b;
    if (n_in >= 2 && in_sizes[0] > in_sizes[1]) { net_in = b; J = a; }
    cann_kernel<<<NBLK, TPB>>>(net_in, J, (float*)d_out);
}

// round 17
// speedup vs baseline: 1.4706x; 1.4706x over previous
#include <cuda_runtime.h>

// CANN recurrent net: 14 PDL-chained step nodes + final node.
//   step t: y = J @ s_{t-1};  U = y/recSum_{t-1} + Iext;  s_t = (0.2 U)^2
//   final:  recSum_14, r_14 = s_14/recSum_14
//
// R11 champion structure (148 CTAs x 384 thr, 1 warp = 1 row, J prefetched to
// registers before griddepcontrol.wait, gate opened after prefetch issue),
// with the dependent phase minimized: NO smem staging, NO __syncthreads.
// The matvec reads s_{t-1} directly via __ldg — L1 is flushed at every kernel
// launch and g_s[(t-1)] is read-only within the step, so warp 0's L2 misses
// seed L1 and the other 11 warps hit L1 on the same 420 lines. Warps are
// fully independent after the wait: publish-per-row-ASAP, earlier CTA exit.

#define Nn     1680
#define NBLK   148
#define TPB    384           // 12 warps
#define ITERS  14
#define KC     0.005f

__device__ float g_s[2][Nn];   // unnormalized s vectors, parity-buffered

__device__ __forceinline__ void pdl_wait() {
    asm volatile("griddepcontrol.wait;" ::: "memory");
}
__device__ __forceinline__ void pdl_launch_dependents() {
    asm volatile("griddepcontrol.launch_dependents;" ::: "memory");
}
__device__ __forceinline__ void stcg(float* p, float v) {
    asm volatile("st.global.cg.f32 [%0], %1;" :: "l"(p), "f"(v) : "memory");
}

__global__ void __launch_bounds__(TPB, 2)
step_kernel(const float* __restrict__ net_in,
            const float* __restrict__ J,
            float* __restrict__ out,
            int t)
{
    const int tid  = threadIdx.x;
    const int lane = tid & 31;
    const int wid  = tid >> 5;
    const int row  = wid * NBLK + (int)blockIdx.x;   // 12*148 = 1776 >= 1680
    const bool active = (row < Nn);

    // ---- prefetch (independent of predecessor): J row -> regs, Iext ----
    // 1680 = 13*128 + 16: 13 float4/lane + 1 scalar for lanes 0..15.
    float4 Jr[13];
    float jtail = 0.f, iext = 0.f;
    if (active) {
        iext = __ldg(&net_in[row]);
        const float* Jrow = J + (size_t)row * Nn;
        const float4* Jp = reinterpret_cast<const float4*>(Jrow);
        #pragma unroll
        for (int j = 0; j < 13; ++j) Jr[j] = __ldg(&Jp[j * 32 + lane]);
        if (lane < 16) jtail = __ldg(&Jrow[1664 + lane]);
    }

    pdl_launch_dependents();   // gate opens after our loads are queued
    pdl_wait();                // predecessor's g_s writes now visible (L2)

    // ---- matvec straight from global (L1-shared across the 12 warps) ----
    if (active) {
        const float* sv = (t == 1) ? (net_in + Nn) : g_s[(t - 1) & 1];
        const float4* s4 = reinterpret_cast<const float4*>(sv);
        float a0 = 0.f, a1 = 0.f, rs = 0.f;
        #pragma unroll
        for (int j = 0; j < 13; ++j) {
            float4 b = __ldg(&s4[j * 32 + lane]);
            rs += (b.x + b.y) + (b.z + b.w);
            if (j & 1) {
                a1 = fmaf(Jr[j].x, b.x, a1); a1 = fmaf(Jr[j].y, b.y, a1);
                a1 = fmaf(Jr[j].z, b.z, a1); a1 = fmaf(Jr[j].w, b.w, a1);
            } else {
                a0 = fmaf(Jr[j].x, b.x, a0); a0 = fmaf(Jr[j].y, b.y, a0);
                a0 = fmaf(Jr[j].z, b.z, a0); a0 = fmaf(Jr[j].w, b.w, a0);
            }
        }
        if (lane < 16) {
            float bt = __ldg(&sv[1664 + lane]);
            rs += bt;
            a1 = fmaf(jtail, bt, a1);
        }
        float acc = a0 + a1;
        #pragma unroll
        for (int o = 16; o; o >>= 1) {
            acc += __shfl_xor_sync(0xffffffffu, acc, o);
            rs  += __shfl_xor_sync(0xffffffffu, rs,  o);
        }
        if (lane == 0) {
            const float invDen = (t == 1) ? 1.0f : 1.0f / (KC * rs);
            float U  = fmaf(acc, invDen, iext);
            float u2 = 0.2f * U;
            float sv2 = u2 * u2;
            stcg(&g_s[t & 1][row], sv2);     // publish the instant the row is done
            if (t == ITERS) out[row] = U;    // U_14
        }
    }
    // no __syncthreads anywhere: warps retire independently -> earlier drain
}

__global__ void __launch_bounds__(448)
final_kernel(float* __restrict__ out)
{
    __shared__ float s_part[14];
    const int tid = threadIdx.x, lane = tid & 31, wid = tid >> 5;

    pdl_wait();

    const float4* s4 = reinterpret_cast<const float4*>(g_s[ITERS & 1]);
    const bool has = tid < Nn / 4;     // 420 of 448 threads carry a float4
    float4 a = make_float4(0.f, 0.f, 0.f, 0.f);
    if (has) a = __ldg(&s4[tid]);      // L1 fresh this launch; L2 has the data
    float v = (a.x + a.y) + (a.z + a.w);
    #pragma unroll
    for (int o = 16; o; o >>= 1) v += __shfl_xor_sync(0xffffffffu, v, o);
    if (lane == 0) s_part[wid] = v;
    __syncthreads();
    float rsum = 0.f;
    #pragma unroll
    for (int w = 0; w < 14; ++w) rsum += s_part[w];
    const float recS = KC * rsum;

    if (tid == 0) out[Nn] = recS;                       // recSum_14
    if (has) {                                          // r_14
        out[Nn + 1 + 4 * tid + 0] = a.x / recS;
        out[Nn + 1 + 4 * tid + 1] = a.y / recS;
        out[Nn + 1 + 4 * tid + 2] = a.z / recS;
        out[Nn + 1 + 4 * tid + 3] = a.w / recS;
    }
}

extern "C" void kernel_launch(void* const* d_in, const int* in_sizes, int n_in,
                              void* d_out, int out_size)
{
    const float* a = (const float*)d_in[0];
    const float* b = (const float*)d_in[1];
    const float* net_in = a;
    const float* J      = b;
    if (n_in >= 2 && in_sizes[0] > in_sizes[1]) { net_in = b; J = a; }
    float* out = (float*)d_out;

    cudaLaunchAttribute attr[1];
    attr[0].id = cudaLaunchAttributeProgrammaticStreamSerialization;
    attr[0].val.programmaticStreamSerializationAllowed = 1;

    cudaLaunchConfig_t cfg = {};
    cfg.gridDim  = dim3(NBLK, 1, 1);
    cfg.blockDim = dim3(TPB, 1, 1);
    cfg.dynamicSmemBytes = 0;
    cfg.stream = 0;            // legacy default stream (captured by harness)
    cfg.attrs = attr;
    cfg.numAttrs = 1;

    for (int t = 1; t <= ITERS; ++t)
        cudaLaunchKernelEx(&cfg, step_kernel, net_in, J, out, t);

    cudaLaunchConfig_t cfgF = cfg;
    cfgF.gridDim  = dim3(1, 1, 1);
    cfgF.blockDim = dim3(448, 1, 1);
    cudaLaunchKernelEx(&cfgF, final_kernel, out);
}